// round 15
// baseline (speedup 1.0000x reference)
#include <cuda_runtime.h>
#include <cuda_fp16.h>
#include <cstdint>

#define NN 100000
#define NH 20000
#define NE 800000
#define NE4 (NE/4)
#define NKA (NH*2)     // hedge-type keys
#define NKB (NN*2)     // node-type keys
#define NBA ((NKA + 1023) / 1024)
#define NBB ((NKB + 1023) / 1024)
#define NOB (NBA + NBB)            // 236 offset blocks
#define NT  ((NN + 127) / 128)     // 782 GRU tiles
#define GRID_GRU 152

// ---------------- static device buffers (zero-initialized at load) ----------
__device__ __align__(16) __half g_xh[(size_t)NN*64];      // fp16 copy of x
__device__ __align__(16) float g_aggA[(size_t)2*NH*64];   // (Σx)/cnt per (t,h)
__device__ __align__(16) __half g_efmh[(size_t)2*NH*64];  // aggA @ Wcomb_t (fp16)
__device__ __align__(16) float g_h[(size_t)NN*64];        // relu(mix)
__device__ int g_cntA[NKA], g_offA[NKA];
__device__ int g_cntB[NKB], g_offB[NKB];
__device__ int g_baseA, g_baseB;
__device__ __align__(16) int g_rankA[NE], g_rankB[NE];
__device__ int g_sortA[NE];   // node ids, sorted by (hedge,type)
__device__ int g_sortB[NE];   // efm element offsets, sorted by (node,type)
// B images
__device__ __align__(16) float g_Bef[2*2*64*32];        // Wcomb_t (swizzled, tf32)
__device__ __align__(16) float g_Bgru[4*256*36];        // GRU B, pitch-36, pair-permuted k
__device__ float g_bias[256];
__device__ float g_bcmix[64];

// ---------------- helpers ---------------------------------------------------
__device__ __forceinline__ float to_tf32(float v) {
    uint32_t u; asm("cvt.rna.tf32.f32 %0, %1;" : "=r"(u) : "f"(v));
    return __uint_as_float(u);
}
__device__ __forceinline__ int swz(int kk, int row) {
    int r = kk & 7;
    int pos = (r < 4) ? (r * 2) : ((r - 4) * 2 + 1);
    int sc = (kk & 24) + pos;
    return (sc + ((row & 3) << 3)) & 31;
}
__device__ __forceinline__ void mma_tf32(float* c, const uint32_t* a,
                                         uint32_t b0, uint32_t b1) {
    asm volatile(
        "mma.sync.aligned.m16n8k8.row.col.f32.tf32.tf32.f32 "
        "{%0,%1,%2,%3}, {%4,%5,%6,%7}, {%8,%9}, {%0,%1,%2,%3};"
        : "+f"(c[0]), "+f"(c[1]), "+f"(c[2]), "+f"(c[3])
        : "r"(a[0]), "r"(a[1]), "r"(a[2]), "r"(a[3]), "r"(b0), "r"(b1));
}
__device__ __forceinline__ float sigf(float x) { return 1.f / (1.f + __expf(-x)); }
__device__ __forceinline__ float tanh_fast(float x) {
    return 1.f - 2.f / (__expf(2.f * x) + 1.f);
}
__device__ __forceinline__ void cp16(uint32_t dst, const void* src) {
    asm volatile("cp.async.cg.shared.global [%0], [%1], 16;" :: "r"(dst), "l"(src));
}
#define CP_COMMIT() asm volatile("cp.async.commit_group;" ::: "memory")
#define CP_WAIT0()  asm volatile("cp.async.wait_group 0;" ::: "memory")

// ---------------- merged prep + histogram (counters pre-zeroed by prior run) -
__global__ void k_prep_hist(const float* __restrict__ Wc, const float* __restrict__ Wmix,
                            const float* __restrict__ bmix, const float* __restrict__ bconv,
                            const float* __restrict__ Wih, const float* __restrict__ Whh,
                            const float* __restrict__ bih, const float* __restrict__ bhh,
                            const int* __restrict__ ni, const int* __restrict__ hi,
                            const int* __restrict__ ea) {
    int idx = blockIdx.x * blockDim.x + threadIdx.x;

    if (idx < 8192) {                     // Bef: [2][2 kc][64 c][32] (swizzled)
        int t = idx >> 12, rem = idx & 4095;
        int kc = rem >> 11, rem2 = rem & 2047, c = rem2 >> 5, kk = rem2 & 31;
        int k = kc * 32 + kk;
        float s = 0.f;
        const float* wr = Wc + t * 4096 + k * 64;
        const float* wm = Wmix + (size_t)t * 64 * 64 + c;
#pragma unroll 8
        for (int m = 0; m < 64; m++) s += wr[m] * wm[(size_t)m * 64];
        g_Bef[((t * 2 + kc) * 64 + c) * 32 + swz(kk, c)] = to_tf32(s);
    } else if (idx < 8192 + 36864) {      // Bgru: [4 kc][256 c][36], pair-permuted k
        int i = idx - 8192;
        int kc = i / 9216, rem = i - kc * 9216;
        int c = rem / 36, kkp = rem - c * 36;
        float v = 0.f;
        if (kkp < 32) {
            int k0 = kkp & ~7, r = kkp & 7;
            int kk = k0 + (r >> 1) + ((r & 1) ? 4 : 0);
            int k = kc * 32 + kk;
            int j = c >> 2, seg = c & 3;
            if (k < 64) {
                if (seg == 0)      v = Wih[k * 192 + j];
                else if (seg == 1) v = Wih[k * 192 + 64 + j];
                else if (seg == 2) v = Wih[k * 192 + 128 + j];
            } else {
                int k2 = k - 64;
                if (seg == 0)      v = Whh[k2 * 192 + j];
                else if (seg == 1) v = Whh[k2 * 192 + 64 + j];
                else if (seg == 3) v = Whh[k2 * 192 + 128 + j];
            }
        }
        g_Bgru[i] = to_tf32(v);
    } else if (idx < 45056 + 256) {       // GRU bias (seg-major)
        int c = idx - 45056;
        int seg = c >> 6, j = c & 63;
        float b;
        if (seg == 0)      b = bih[j] + bhh[j];
        else if (seg == 1) b = bih[64 + j] + bhh[64 + j];
        else if (seg == 2) b = bih[128 + j];
        else               b = bhh[128 + j];
        g_bias[c] = b;
    } else if (idx < 45056 + 256 + 64) {  // folded mix bias
        int j = idx - 45056 - 256;
        float s = bmix[j];
        for (int k = 0; k < 128; k++) s += bconv[k] * Wmix[k * 64 + j];
        g_bcmix[j] = s;
    }

    // ---- histogram + rank capture (4 edges/thread) ----
    if (idx < NE4) {
        int4 n = ((const int4*)ni)[idx];
        int4 h = ((const int4*)hi)[idx];
        int4 t = ((const int4*)ea)[idx];
        int4 ra, rb;
        ra.x = atomicAdd(&g_cntA[h.x * 2 + t.x], 1);
        ra.y = atomicAdd(&g_cntA[h.y * 2 + t.y], 1);
        ra.z = atomicAdd(&g_cntA[h.z * 2 + t.z], 1);
        ra.w = atomicAdd(&g_cntA[h.w * 2 + t.w], 1);
        rb.x = atomicAdd(&g_cntB[n.x * 2 + t.x], 1);
        rb.y = atomicAdd(&g_cntB[n.y * 2 + t.y], 1);
        rb.z = atomicAdd(&g_cntB[n.z * 2 + t.z], 1);
        rb.w = atomicAdd(&g_cntB[n.w * 2 + t.w], 1);
        ((int4*)g_rankA)[idx] = ra;
        ((int4*)g_rankB)[idx] = rb;
    }
}

// ---------------- offsets: block scan + atomic range claim + x->fp16 --------
__global__ __launch_bounds__(1024) void k_offsets(const float* __restrict__ x) {
    cudaTriggerProgrammaticLaunchCompletion();   // let k_perm prologue start
    __shared__ int sm[1024];
    __shared__ int blockBase;
    int b = blockIdx.x;
    const int* cnt; int* off; int n; int* gbase;
    if (b < NBA) { cnt = g_cntA; off = g_offA; n = NKA; gbase = &g_baseA; }
    else { cnt = g_cntB; off = g_offB; n = NKB; gbase = &g_baseB; b -= NBA; }
    int tid = threadIdx.x;
    int i = b * 1024 + tid;
    int v = (i < n) ? cnt[i] : 0;
    sm[tid] = v;
    __syncthreads();
    for (int d = 1; d < 1024; d <<= 1) {
        int t = (tid >= d) ? sm[tid - d] : 0;
        __syncthreads();
        sm[tid] += t;
        __syncthreads();
    }
    if (tid == 1023) blockBase = atomicAdd(gbase, sm[1023]);
    // x -> fp16 conversion: independent work, hides under scan/claim latency.
    // 236 blocks x 1024 threads; thread g handles one uint4 (8 floats) if g<800000.
    {
        int gtid = blockIdx.x * 1024 + tid;
        if (gtid < 800000) {
            const float4* src = (const float4*)x;
            float4 a = src[gtid * 2 + 0];
            float4 bq = src[gtid * 2 + 1];
            __align__(16) __half2 hh[4];
            hh[0] = __floats2half2_rn(a.x, a.y);
            hh[1] = __floats2half2_rn(a.z, a.w);
            hh[2] = __floats2half2_rn(bq.x, bq.y);
            hh[3] = __floats2half2_rn(bq.z, bq.w);
            ((uint4*)g_xh)[gtid] = *(const uint4*)hh;
        }
        // remaining 3.2M floats handled by strided second pass
        for (int g2 = gtid + NOB * 1024; g2 < 800000; g2 += NOB * 1024) {
            const float4* src = (const float4*)x;
            float4 a = src[g2 * 2 + 0];
            float4 bq = src[g2 * 2 + 1];
            __align__(16) __half2 hh[4];
            hh[0] = __floats2half2_rn(a.x, a.y);
            hh[1] = __floats2half2_rn(a.z, a.w);
            hh[2] = __floats2half2_rn(bq.x, bq.y);
            hh[3] = __floats2half2_rn(bq.z, bq.w);
            ((uint4*)g_xh)[g2] = *(const uint4*)hh;
        }
    }
    __syncthreads();
    if (i < n) off[i] = blockBase + sm[tid] - v;
}

// ---------------- permute (PDL secondary): prologue loads, then scatter -----
__global__ void k_perm(const int* __restrict__ ni, const int* __restrict__ hi,
                       const int* __restrict__ ea) {
    cudaTriggerProgrammaticLaunchCompletion();   // let k_gatherA prologue start
    int i = blockIdx.x * 256 + threadIdx.x;
    int4 n = {}, h = {}, t = {}, ra = {}, rb = {};
    if (i < NE4) {
        n = ((const int4*)ni)[i];
        h = ((const int4*)hi)[i];
        t = ((const int4*)ea)[i];
        ra = ((const int4*)g_rankA)[i];
        rb = ((const int4*)g_rankB)[i];
    }
    cudaGridDependencySynchronize();             // wait for k_offsets (g_off*)
    if (i >= NE4) return;
    g_sortA[g_offA[h.x * 2 + t.x] + ra.x] = n.x;
    g_sortA[g_offA[h.y * 2 + t.y] + ra.y] = n.y;
    g_sortA[g_offA[h.z * 2 + t.z] + ra.z] = n.z;
    g_sortA[g_offA[h.w * 2 + t.w] + ra.w] = n.w;
    g_sortB[g_offB[n.x * 2 + t.x] + rb.x] = (t.x * NH + h.x) * 64;
    g_sortB[g_offB[n.y * 2 + t.y] + rb.y] = (t.y * NH + h.y) * 64;
    g_sortB[g_offB[n.z * 2 + t.z] + rb.z] = (t.z * NH + h.z) * 64;
    g_sortB[g_offB[n.w * 2 + t.w] + rb.w] = (t.w * NH + h.w) * 64;
}

// ---------------- gather A (PDL secondary): fp16 x rows ---------------------
__global__ __launch_bounds__(256) void k_gatherA() {
    cudaTriggerProgrammaticLaunchCompletion();   // let k_mma_ef prologue start
    int key = (blockIdx.x * 256 + threadIdx.x) >> 5;
    int lane = threadIdx.x & 31;
    int half = lane >> 4, sub = lane & 15;
    int base = 0, cnt = 0;
    if (key < NKA) { base = g_offA[key]; cnt = g_cntA[key]; }
    cudaGridDependencySynchronize();             // wait for k_perm (g_sortA)
    if (key >= NKA) return;
    int t = key & 1, h = key >> 1;
    const __half* xb = g_xh + sub * 4;
    float4 acc = make_float4(0.f, 0.f, 0.f, 0.f);
    int i = 0;
    for (; i + 4 <= cnt; i += 4) {
        int n0 = g_sortA[base + i + half];
        int n1 = g_sortA[base + i + 2 + half];
        uint2 r0 = *(const uint2*)(xb + (size_t)n0 * 64);
        uint2 r1 = *(const uint2*)(xb + (size_t)n1 * 64);
        float2 f0 = __half22float2(*reinterpret_cast<__half2*>(&r0.x));
        float2 f1 = __half22float2(*reinterpret_cast<__half2*>(&r0.y));
        float2 f2 = __half22float2(*reinterpret_cast<__half2*>(&r1.x));
        float2 f3 = __half22float2(*reinterpret_cast<__half2*>(&r1.y));
        acc.x += f0.x + f2.x; acc.y += f0.y + f2.y;
        acc.z += f1.x + f3.x; acc.w += f1.y + f3.y;
    }
    for (; i < cnt; i += 2) {
        int idx = i + half;
        if (idx < cnt) {
            int n = g_sortA[base + idx];
            uint2 r0 = *(const uint2*)(xb + (size_t)n * 64);
            float2 f0 = __half22float2(*reinterpret_cast<__half2*>(&r0.x));
            float2 f1 = __half22float2(*reinterpret_cast<__half2*>(&r0.y));
            acc.x += f0.x; acc.y += f0.y; acc.z += f1.x; acc.w += f1.y;
        }
    }
    acc.x += __shfl_xor_sync(0xffffffffu, acc.x, 16);
    acc.y += __shfl_xor_sync(0xffffffffu, acc.y, 16);
    acc.z += __shfl_xor_sync(0xffffffffu, acc.z, 16);
    acc.w += __shfl_xor_sync(0xffffffffu, acc.w, 16);
    if (half == 0) {
        float s = (cnt > 0) ? 1.f / (float)cnt : 0.f;
        acc.x *= s; acc.y *= s; acc.z *= s; acc.w *= s;
        *(float4*)&g_aggA[((size_t)t * NH + h) * 64 + sub * 4] = acc;
    }
}

// ---------------- GEMM: efm = aggA @ Wcomb_t (fp16 out), PDL secondary ------
__global__ __launch_bounds__(256) void k_mma_ef() {
    __shared__ __align__(16) float As[128][32];
    __shared__ __align__(16) float Bs[2][64][32];
    int tid = threadIdx.x;
    int lane = tid & 31, warp = tid >> 5;
    int warpM = warp >> 1, warpN = warp & 1;
    int g = lane >> 2, t4 = lane & 3;
    int rot = (g & 3) << 3;
    int n0 = blockIdx.x * 128;
    int ty = blockIdx.y;

    {
        const float4* src = (const float4*)&g_Bef[ty * 4096];
        float4* dst = (float4*)&Bs[0][0][0];
        for (int i = tid; i < 1024; i += 256) dst[i] = src[i];
    }
    cudaGridDependencySynchronize();   // wait for gatherA's aggA

    float acc[2][4][4] = {};
    for (int kc = 0; kc < 2; kc++) {
        __syncthreads();
        for (int i = tid; i < 4096; i += 256) {
            int m = i >> 5, kk = i & 31;
            int n = n0 + m;
            float v = (n < NH) ? g_aggA[((size_t)ty * NH + n) * 64 + kc * 32 + kk] : 0.f;
            As[m][swz(kk, m)] = to_tf32(v);
        }
        __syncthreads();
#pragma unroll
        for (int s = 0; s < 4; s++) {
            int pc = (s * 8 + 2 * t4 + rot) & 31;
            uint32_t a[2][4];
#pragma unroll
            for (int mt = 0; mt < 2; mt++) {
                int r = warpM * 32 + mt * 16 + g;
                float2 lo = *(const float2*)&As[r][pc];
                float2 hi = *(const float2*)&As[r + 8][pc];
                a[mt][0] = __float_as_uint(lo.x); a[mt][1] = __float_as_uint(hi.x);
                a[mt][2] = __float_as_uint(lo.y); a[mt][3] = __float_as_uint(hi.y);
            }
#pragma unroll
            for (int nt = 0; nt < 4; nt++) {
                int c = warpN * 32 + nt * 8 + g;
                float2 b = *(const float2*)&Bs[kc][c][pc];
                uint32_t b0 = __float_as_uint(b.x), b1 = __float_as_uint(b.y);
                mma_tf32(acc[0][nt], a[0], b0, b1);
                mma_tf32(acc[1][nt], a[1], b0, b1);
            }
        }
    }
#pragma unroll
    for (int mt = 0; mt < 2; mt++) {
        int r = n0 + warpM * 32 + mt * 16 + g;
#pragma unroll
        for (int nt = 0; nt < 4; nt++) {
            int c = warpN * 32 + nt * 8 + 2 * t4;
            if (r < NH)
                *(__half2*)&g_efmh[((size_t)ty * NH + r) * 64 + c] =
                    __floats2half2_rn(acc[mt][nt][0], acc[mt][nt][1]);
            if (r + 8 < NH)
                *(__half2*)&g_efmh[((size_t)ty * NH + r + 8) * 64 + c] =
                    __floats2half2_rn(acc[mt][nt][2], acc[mt][nt][3]);
        }
    }
}

// ---------------- gather B (PDL secondary): fp16 rows -----------------------
__global__ __launch_bounds__(256) void k_gatherB() {
    cudaTriggerProgrammaticLaunchCompletion();   // let k_gru prologue start
    int node = (blockIdx.x * 256 + threadIdx.x) >> 5;
    int lane = threadIdx.x & 31;
    int half = lane >> 4, sub = lane & 15;
    int base0 = 0, cnt0 = 0, base1 = 0, cnt1 = 0;
    if (node < NN) {
        base0 = g_offB[node * 2];     cnt0 = g_cntB[node * 2];
        base1 = g_offB[node * 2 + 1]; cnt1 = g_cntB[node * 2 + 1];
    }
    cudaGridDependencySynchronize();             // wait for k_mma_ef (g_efmh)
    if (node >= NN) return;
    const __half* eb = g_efmh + sub * 4;
    float4 tot = make_float4(0.f, 0.f, 0.f, 0.f);
#pragma unroll
    for (int t = 0; t < 2; t++) {
        int base = t ? base1 : base0;
        int cnt  = t ? cnt1 : cnt0;
        float4 acc = make_float4(0.f, 0.f, 0.f, 0.f);
        int i = 0;
        for (; i + 4 <= cnt; i += 4) {
            int o0 = g_sortB[base + i + half];
            int o1 = g_sortB[base + i + 2 + half];
            uint2 r0 = *(const uint2*)(eb + o0);
            uint2 r1 = *(const uint2*)(eb + o1);
            float2 f0 = __half22float2(*reinterpret_cast<__half2*>(&r0.x));
            float2 f1 = __half22float2(*reinterpret_cast<__half2*>(&r0.y));
            float2 f2 = __half22float2(*reinterpret_cast<__half2*>(&r1.x));
            float2 f3 = __half22float2(*reinterpret_cast<__half2*>(&r1.y));
            acc.x += f0.x + f2.x; acc.y += f0.y + f2.y;
            acc.z += f1.x + f3.x; acc.w += f1.y + f3.y;
        }
        for (; i < cnt; i += 2) {
            int idx = i + half;
            if (idx < cnt) {
                int o = g_sortB[base + idx];
                uint2 r0 = *(const uint2*)(eb + o);
                float2 f0 = __half22float2(*reinterpret_cast<__half2*>(&r0.x));
                float2 f1 = __half22float2(*reinterpret_cast<__half2*>(&r0.y));
                acc.x += f0.x; acc.y += f0.y; acc.z += f1.x; acc.w += f1.y;
            }
        }
        float s = (cnt > 0) ? 1.f / (float)cnt : 0.f;
        tot.x += acc.x * s; tot.y += acc.y * s;
        tot.z += acc.z * s; tot.w += acc.w * s;
    }
    tot.x += __shfl_xor_sync(0xffffffffu, tot.x, 16);
    tot.y += __shfl_xor_sync(0xffffffffu, tot.y, 16);
    tot.z += __shfl_xor_sync(0xffffffffu, tot.z, 16);
    tot.w += __shfl_xor_sync(0xffffffffu, tot.w, 16);
    if (half == 0) {
        float4 b = *(const float4*)&g_bcmix[sub * 4];
        float4 o;
        o.x = fmaxf(tot.x + b.x, 0.f); o.y = fmaxf(tot.y + b.y, 0.f);
        o.z = fmaxf(tot.z + b.z, 0.f); o.w = fmaxf(tot.w + b.w, 0.f);
        *(float4*)&g_h[(size_t)node * 64 + sub * 4] = o;
    }
}

// ---------------- persistent GRU: B-resident, PDL secondary -----------------
// Also resets counters at the end (for the next replay of the graph).
#define OF_AS   36864
#define OF_WRO  46080
#define OF_SRED 46336
#define OF_HS   46848
#define GRU_SMEM ((46848 + 8704) * 4)
__global__ __launch_bounds__(512) void k_gru(const float* __restrict__ h_prev,
                                             const float* __restrict__ Wro,
                                             const float* __restrict__ bro,
                                             float* __restrict__ out_h,
                                             float* __restrict__ out3) {
    extern __shared__ __align__(16) float sm[];
    uint32_t smb;
    asm("{ .reg .u64 t; cvta.to.shared.u64 t, %1; cvt.u32.u64 %0, t; }"
        : "=r"(smb) : "l"(sm));
    int tid = threadIdx.x;
    int lane = tid & 31, warp = tid >> 5;
    int warpM = warp >> 2, warpN = warp & 3;
    int g = lane >> 2, t = lane & 3;

    for (int i = tid; i < 9216; i += 512)
        cp16(smb + (uint32_t)i * 16, (const char*)g_Bgru + (size_t)i * 16);
    CP_COMMIT();
    if (tid < 256) {
        int j = tid >> 2, c = tid & 3;
        sm[OF_WRO + tid] = (c < 3) ? __ldg(&Wro[j * 64 + c]) : 0.f;
    }
    sm[OF_SRED + tid] = 0.f;
    float brd0 = __ldg(&bro[0]), brd1 = __ldg(&bro[1]), brd2 = __ldg(&bro[2]);

    cudaGridDependencySynchronize();   // wait for gatherB's g_h

#define STAGE_A(ptile, pkc) do {                                               \
        int _kc = (pkc);                                                       \
        uint32_t _dst = smb + (OF_AS + (_kc & 1) * 4608) * 4;                  \
        for (int i = tid; i < 1024; i += 512) {                                \
            int m = i >> 3, q = i & 7;                                         \
            int n = (ptile) * 128 + m;                                         \
            int nc = (n < NN) ? n : (NN - 1);                                  \
            const float* src = (_kc < 2)                                       \
                ? &g_h[(size_t)nc * 64 + _kc * 32 + q * 4]                     \
                : &h_prev[(size_t)nc * 64 + (_kc - 2) * 32 + q * 4];           \
            cp16(_dst + (uint32_t)(m * 144 + q * 16), src);                    \
        }                                                                      \
    } while (0)

    int tile = blockIdx.x;
    if (tile < NT) STAGE_A(tile, 0);
    CP_COMMIT();

    for (; tile < NT; tile += GRID_GRU) {
        int n0 = tile * 128;
        float acc[2][8][4] = {};
        for (int kc = 0; kc < 4; kc++) {
            CP_WAIT0();
            __syncthreads();
            if (kc < 3) { STAGE_A(tile, kc + 1); CP_COMMIT(); }
            const float* As = sm + OF_AS + (kc & 1) * 4608;
            const float* Bb = sm + kc * 9216;
#pragma unroll
            for (int s = 0; s < 4; s++) {
                int k0 = s * 8;
                uint32_t a[2][4];
#pragma unroll
                for (int mt = 0; mt < 2; mt++) {
                    int r = warpM * 32 + mt * 16 + g;
                    a[mt][0] = __float_as_uint(As[r * 36 + k0 + t]);
                    a[mt][1] = __float_as_uint(As[(r + 8) * 36 + k0 + t]);
                    a[mt][2] = __float_as_uint(As[r * 36 + k0 + t + 4]);
                    a[mt][3] = __float_as_uint(As[(r + 8) * 36 + k0 + t + 4]);
                }
#pragma unroll
                for (int nt = 0; nt < 8; nt++) {
                    int c = warpN * 64 + nt * 8 + g;
                    float2 bb = *(const float2*)&Bb[c * 36 + k0 + 2 * t];
                    mma_tf32(acc[0][nt], a[0],
                             __float_as_uint(bb.x), __float_as_uint(bb.y));
                    mma_tf32(acc[1][nt], a[1],
                             __float_as_uint(bb.x), __float_as_uint(bb.y));
                }
            }
        }

        const float* Ab0 = sm + OF_AS;
        const float* Ab1 = sm + OF_AS + 4608;
        float p[2][2][3] = {};
        bool even = (t & 1) == 0;
#pragma unroll
        for (int mt = 0; mt < 2; mt++) {
#pragma unroll
            for (int nt = 0; nt < 8; nt++) {
                int j = warpN * 16 + nt * 2 + (t >> 1);
                float br = g_bias[j], bz = g_bias[64 + j];
                float bn = g_bias[128 + j], bh = g_bias[192 + j];
                float w0 = sm[OF_WRO + j * 4 + 0];
                float w1 = sm[OF_WRO + j * 4 + 1];
                float w2 = sm[OF_WRO + j * 4 + 2];
#pragma unroll
                for (int rh = 0; rh < 2; rh++) {
                    int m = warpM * 32 + mt * 16 + rh * 8 + g;
                    float v0 = acc[mt][nt][rh * 2 + 0];
                    float v1 = acc[mt][nt][rh * 2 + 1];
                    float o0 = __shfl_xor_sync(0xffffffffu, v0, 1);
                    float o1 = __shfl_xor_sync(0xffffffffu, v1, 1);
                    float hn = 0.f;
                    if (even) {
                        float r_ = sigf(v0 + br);
                        float z_ = sigf(v1 + bz);
                        float nv = tanh_fast((o0 + bn) + r_ * (o1 + bh));
                        float hp = (j < 32) ? Ab0[m * 36 + j] : Ab1[m * 36 + j - 32];
                        hn = (1.f - z_) * nv + z_ * hp;
                        sm[OF_HS + m * 68 + j] = hn;
                    }
                    p[mt][rh][0] += hn * w0;
                    p[mt][rh][1] += hn * w1;
                    p[mt][rh][2] += hn * w2;
                }
            }
        }
#pragma unroll
        for (int mt = 0; mt < 2; mt++)
#pragma unroll
            for (int rh = 0; rh < 2; rh++)
#pragma unroll
                for (int c = 0; c < 3; c++) {
                    float v = p[mt][rh][c] + __shfl_xor_sync(0xffffffffu, p[mt][rh][c], 2);
                    if (t == 0)
                        atomicAdd(&sm[OF_SRED + (warpM * 32 + mt * 16 + rh * 8 + g) * 4 + c], v);
                }
        __syncthreads();

        {
            int pt = tile + GRID_GRU;
            if (pt < NT) { STAGE_A(pt, 0); CP_COMMIT(); }
        }

        for (int i = tid; i < 2048; i += 512) {
            int m = i >> 4, q = i & 15;
            int n = n0 + m;
            if (n < NN)
                *(float4*)&out_h[(size_t)n * 64 + q * 4] =
                    *(const float4*)&sm[OF_HS + m * 68 + q * 4];
        }
        {
            int nd = tid >> 2, c = tid & 3;
            int n = n0 + nd;
            if (c < 3 && n < NN)
                out3[(size_t)n * 3 + c] = sm[OF_SRED + tid] +
                                          (c == 0 ? brd0 : (c == 1 ? brd1 : brd2));
        }
        __syncthreads();
        sm[OF_SRED + tid] = 0.f;
    }
#undef STAGE_A

    // ---- reset counters for the next run (nothing reads them after here) ----
    {
        int gstride = GRID_GRU * 512;
        int gtid = blockIdx.x * 512 + tid;
        for (int i = gtid; i < NKA; i += gstride) g_cntA[i] = 0;
        for (int i = gtid; i < NKB; i += gstride) g_cntB[i] = 0;
        if (gtid == 0) { g_baseA = 0; g_baseB = 0; }
    }
}

// ---------------- launch -----------------------------------------------------
extern "C" void kernel_launch(void* const* d_in, const int* in_sizes, int n_in,
                              void* d_out, int out_size) {
    const float* x       = (const float*)d_in[0];
    const float* h_prev  = (const float*)d_in[1];
    const int* node_idx  = (const int*)d_in[2];
    const int* hedge_idx = (const int*)d_in[3];
    const int* edge_attr = (const int*)d_in[4];
    const float* W_conv  = (const float*)d_in[5];
    const float* b_conv  = (const float*)d_in[6];
    const float* W_mix   = (const float*)d_in[7];
    const float* b_mix   = (const float*)d_in[8];
    const float* W_ih    = (const float*)d_in[9];
    const float* W_hh    = (const float*)d_in[10];
    const float* b_ih    = (const float*)d_in[11];
    const float* b_hh    = (const float*)d_in[12];
    const float* W_ro    = (const float*)d_in[13];
    const float* b_ro    = (const float*)d_in[14];

    float* h_next = (float*)d_out;
    float* out3   = (float*)d_out + (size_t)NN * 64;

    cudaFuncSetAttribute(k_gru, cudaFuncAttributeMaxDynamicSharedMemorySize, GRU_SMEM);

    cudaLaunchAttribute pdl[1];
    pdl[0].id = cudaLaunchAttributeProgrammaticStreamSerialization;
    pdl[0].val.programmaticStreamSerializationAllowed = 1;

    k_prep_hist<<<(NE4 + 255) / 256, 256>>>(W_conv, W_mix, b_mix, b_conv,
                                            W_ih, W_hh, b_ih, b_hh,
                                            node_idx, hedge_idx, edge_attr);
    k_offsets<<<NOB, 1024>>>(x);
    {
        cudaLaunchConfig_t cfg = {};
        cfg.gridDim = dim3((NE4 + 255) / 256);
        cfg.blockDim = dim3(256);
        cfg.attrs = pdl; cfg.numAttrs = 1;
        cudaLaunchKernelEx(&cfg, k_perm, node_idx, hedge_idx, edge_attr);
    }
    {
        cudaLaunchConfig_t cfg = {};
        cfg.gridDim = dim3((NKA * 32 + 255) / 256);
        cfg.blockDim = dim3(256);
        cfg.attrs = pdl; cfg.numAttrs = 1;
        cudaLaunchKernelEx(&cfg, k_gatherA);
    }
    {
        cudaLaunchConfig_t cfg = {};
        cfg.gridDim = dim3((NH + 127) / 128, 2);
        cfg.blockDim = dim3(256);
        cfg.attrs = pdl; cfg.numAttrs = 1;
        cudaLaunchKernelEx(&cfg, k_mma_ef);
    }
    {
        cudaLaunchConfig_t cfg = {};
        cfg.gridDim = dim3((NN * 32 + 255) / 256);
        cfg.blockDim = dim3(256);
        cfg.attrs = pdl; cfg.numAttrs = 1;
        cudaLaunchKernelEx(&cfg, k_gatherB);
    }
    {
        cudaLaunchConfig_t cfg = {};
        cfg.gridDim = dim3(GRID_GRU);
        cfg.blockDim = dim3(512);
        cfg.dynamicSmemBytes = GRU_SMEM;
        cfg.attrs = pdl; cfg.numAttrs = 1;
        cudaLaunchKernelEx(&cfg, k_gru, h_prev, W_ro, b_ro, h_next, out3);
    }
}

// round 16
// speedup vs baseline: 1.0152x; 1.0152x over previous
#include <cuda_runtime.h>
#include <cuda_fp16.h>
#include <cstdint>

#define NN 100000
#define NH 20000
#define NE 800000
#define NE4 (NE/4)
#define NKA (NH*2)     // hedge-type keys
#define NKB (NN*2)     // node-type keys
#define NBA ((NKA + 1023) / 1024)
#define NBB ((NKB + 1023) / 1024)
#define NT  ((NN + 127) / 128)   // 782 GRU tiles
#define GRID_GRU 152

// ---------------- static device buffers (zero-init at load) -----------------
__device__ __align__(16) float g_aggA[(size_t)2*NH*64];   // (Σx)/cnt per (t,h)
__device__ __align__(16) __half g_efmh[(size_t)2*NH*64];  // aggA @ Wcomb_t (fp16)
__device__ __align__(16) float g_h[(size_t)NN*64];        // relu(mix)
__device__ int g_cntA[NKA], g_offA[NKA];
__device__ int g_cntB[NKB], g_offB[NKB];
__device__ int g_baseA, g_baseB;
__device__ __align__(16) int g_rankA[NE], g_rankB[NE];
__device__ int g_sortA[NE];   // node ids, sorted by (hedge,type)
__device__ int g_sortB[NE];   // efm element offsets, sorted by (node,type)
// B images
__device__ __align__(16) float g_Bef[2*2*64*32];        // Wcomb_t (swizzled, tf32)
__device__ __align__(16) float g_Bgru[4*256*36];        // GRU B, pitch-36, pair-permuted k
__device__ float g_bias[256];
__device__ float g_bcmix[64];

// ---------------- helpers ---------------------------------------------------
__device__ __forceinline__ float to_tf32(float v) {
    uint32_t u; asm("cvt.rna.tf32.f32 %0, %1;" : "=r"(u) : "f"(v));
    return __uint_as_float(u);
}
__device__ __forceinline__ int swz(int kk, int row) {
    int r = kk & 7;
    int pos = (r < 4) ? (r * 2) : ((r - 4) * 2 + 1);
    int sc = (kk & 24) + pos;
    return (sc + ((row & 3) << 3)) & 31;
}
__device__ __forceinline__ void mma_tf32(float* c, const uint32_t* a,
                                         uint32_t b0, uint32_t b1) {
    asm volatile(
        "mma.sync.aligned.m16n8k8.row.col.f32.tf32.tf32.f32 "
        "{%0,%1,%2,%3}, {%4,%5,%6,%7}, {%8,%9}, {%0,%1,%2,%3};"
        : "+f"(c[0]), "+f"(c[1]), "+f"(c[2]), "+f"(c[3])
        : "r"(a[0]), "r"(a[1]), "r"(a[2]), "r"(a[3]), "r"(b0), "r"(b1));
}
__device__ __forceinline__ float sigf(float x) { return 1.f / (1.f + __expf(-x)); }
__device__ __forceinline__ float tanh_fast(float x) {
    return 1.f - 2.f / (__expf(2.f * x) + 1.f);
}
__device__ __forceinline__ void cp16(uint32_t dst, const void* src) {
    asm volatile("cp.async.cg.shared.global [%0], [%1], 16;" :: "r"(dst), "l"(src));
}
#define CP_COMMIT() asm volatile("cp.async.commit_group;" ::: "memory")
#define CP_WAIT0()  asm volatile("cp.async.wait_group 0;" ::: "memory")

// ---------------- merged prep + histogram (counters zeroed by prior gru) ----
__global__ void k_prep_hist(const float* __restrict__ Wc, const float* __restrict__ Wmix,
                            const float* __restrict__ bmix, const float* __restrict__ bconv,
                            const float* __restrict__ Wih, const float* __restrict__ Whh,
                            const float* __restrict__ bih, const float* __restrict__ bhh,
                            const int* __restrict__ ni, const int* __restrict__ hi,
                            const int* __restrict__ ea) {
    int idx = blockIdx.x * blockDim.x + threadIdx.x;

    if (idx < 8192) {                     // Bef: [2][2 kc][64 c][32] (swizzled)
        int t = idx >> 12, rem = idx & 4095;
        int kc = rem >> 11, rem2 = rem & 2047, c = rem2 >> 5, kk = rem2 & 31;
        int k = kc * 32 + kk;
        float s = 0.f;
        const float* wr = Wc + t * 4096 + k * 64;
        const float* wm = Wmix + (size_t)t * 64 * 64 + c;
#pragma unroll 8
        for (int m = 0; m < 64; m++) s += wr[m] * wm[(size_t)m * 64];
        g_Bef[((t * 2 + kc) * 64 + c) * 32 + swz(kk, c)] = to_tf32(s);
    } else if (idx < 8192 + 36864) {      // Bgru: [4 kc][256 c][36], pair-permuted k
        int i = idx - 8192;
        int kc = i / 9216, rem = i - kc * 9216;
        int c = rem / 36, kkp = rem - c * 36;
        float v = 0.f;
        if (kkp < 32) {
            int k0 = kkp & ~7, r = kkp & 7;
            int kk = k0 + (r >> 1) + ((r & 1) ? 4 : 0);
            int k = kc * 32 + kk;
            int j = c >> 2, seg = c & 3;
            if (k < 64) {
                if (seg == 0)      v = Wih[k * 192 + j];
                else if (seg == 1) v = Wih[k * 192 + 64 + j];
                else if (seg == 2) v = Wih[k * 192 + 128 + j];
            } else {
                int k2 = k - 64;
                if (seg == 0)      v = Whh[k2 * 192 + j];
                else if (seg == 1) v = Whh[k2 * 192 + 64 + j];
                else if (seg == 3) v = Whh[k2 * 192 + 128 + j];
            }
        }
        g_Bgru[i] = to_tf32(v);
    } else if (idx < 45056 + 256) {       // GRU bias (seg-major)
        int c = idx - 45056;
        int seg = c >> 6, j = c & 63;
        float b;
        if (seg == 0)      b = bih[j] + bhh[j];
        else if (seg == 1) b = bih[64 + j] + bhh[64 + j];
        else if (seg == 2) b = bih[128 + j];
        else               b = bhh[128 + j];
        g_bias[c] = b;
    } else if (idx < 45056 + 256 + 64) {  // folded mix bias
        int j = idx - 45056 - 256;
        float s = bmix[j];
        for (int k = 0; k < 128; k++) s += bconv[k] * Wmix[k * 64 + j];
        g_bcmix[j] = s;
    }

    // ---- histogram + rank capture (4 edges/thread) ----
    if (idx < NE4) {
        int4 n = ((const int4*)ni)[idx];
        int4 h = ((const int4*)hi)[idx];
        int4 t = ((const int4*)ea)[idx];
        int4 ra, rb;
        ra.x = atomicAdd(&g_cntA[h.x * 2 + t.x], 1);
        ra.y = atomicAdd(&g_cntA[h.y * 2 + t.y], 1);
        ra.z = atomicAdd(&g_cntA[h.z * 2 + t.z], 1);
        ra.w = atomicAdd(&g_cntA[h.w * 2 + t.w], 1);
        rb.x = atomicAdd(&g_cntB[n.x * 2 + t.x], 1);
        rb.y = atomicAdd(&g_cntB[n.y * 2 + t.y], 1);
        rb.z = atomicAdd(&g_cntB[n.z * 2 + t.z], 1);
        rb.w = atomicAdd(&g_cntB[n.w * 2 + t.w], 1);
        ((int4*)g_rankA)[idx] = ra;
        ((int4*)g_rankB)[idx] = rb;
    }
}

// ---------------- parallel offsets: block scan + atomic range claim ---------
__global__ __launch_bounds__(1024) void k_offsets() {
    cudaTriggerProgrammaticLaunchCompletion();   // let k_perm prologue start
    __shared__ int sm[1024];
    __shared__ int blockBase;
    int b = blockIdx.x;
    const int* cnt; int* off; int n; int* gbase;
    if (b < NBA) { cnt = g_cntA; off = g_offA; n = NKA; gbase = &g_baseA; }
    else { b -= NBA; cnt = g_cntB; off = g_offB; n = NKB; gbase = &g_baseB; }
    int tid = threadIdx.x;
    int i = b * 1024 + tid;
    int v = (i < n) ? cnt[i] : 0;
    sm[tid] = v;
    __syncthreads();
    for (int d = 1; d < 1024; d <<= 1) {
        int t = (tid >= d) ? sm[tid - d] : 0;
        __syncthreads();
        sm[tid] += t;
        __syncthreads();
    }
    if (tid == 1023) blockBase = atomicAdd(gbase, sm[1023]);
    __syncthreads();
    if (i < n) off[i] = blockBase + sm[tid] - v;
}

// ---------------- permute (PDL secondary): prologue loads, then scatter -----
__global__ void k_perm(const int* __restrict__ ni, const int* __restrict__ hi,
                       const int* __restrict__ ea) {
    cudaTriggerProgrammaticLaunchCompletion();   // let k_gatherA prologue start
    int i = blockIdx.x * 256 + threadIdx.x;
    int4 n = {}, h = {}, t = {}, ra = {}, rb = {};
    if (i < NE4) {
        n = ((const int4*)ni)[i];
        h = ((const int4*)hi)[i];
        t = ((const int4*)ea)[i];
        ra = ((const int4*)g_rankA)[i];
        rb = ((const int4*)g_rankB)[i];
    }
    cudaGridDependencySynchronize();             // wait for k_offsets (g_off*)
    if (i >= NE4) return;
    g_sortA[g_offA[h.x * 2 + t.x] + ra.x] = n.x;
    g_sortA[g_offA[h.y * 2 + t.y] + ra.y] = n.y;
    g_sortA[g_offA[h.z * 2 + t.z] + ra.z] = n.z;
    g_sortA[g_offA[h.w * 2 + t.w] + ra.w] = n.w;
    g_sortB[g_offB[n.x * 2 + t.x] + rb.x] = (t.x * NH + h.x) * 64;
    g_sortB[g_offB[n.y * 2 + t.y] + rb.y] = (t.y * NH + h.y) * 64;
    g_sortB[g_offB[n.z * 2 + t.z] + rb.z] = (t.z * NH + h.z) * 64;
    g_sortB[g_offB[n.w * 2 + t.w] + rb.w] = (t.w * NH + h.w) * 64;
}

// ---------------- gather A (PDL secondary): fp32 x rows ---------------------
__global__ __launch_bounds__(256) void k_gatherA(const float* __restrict__ x) {
    cudaTriggerProgrammaticLaunchCompletion();   // let k_mma_ef prologue start
    int key = (blockIdx.x * 256 + threadIdx.x) >> 5;
    int lane = threadIdx.x & 31;
    int half = lane >> 4, sub = lane & 15;
    int base = 0, cnt = 0;
    if (key < NKA) { base = g_offA[key]; cnt = g_cntA[key]; }  // prologue
    cudaGridDependencySynchronize();             // wait for k_perm (g_sortA)
    if (key >= NKA) return;
    int t = key & 1, h = key >> 1;
    const float* xb = x + sub * 4;
    float4 acc = make_float4(0.f, 0.f, 0.f, 0.f);
    int i = 0;
    for (; i + 4 <= cnt; i += 4) {
        int n0 = g_sortA[base + i + half];
        int n1 = g_sortA[base + i + 2 + half];
        float4 v0 = *(const float4*)(xb + (size_t)n0 * 64);
        float4 v1 = *(const float4*)(xb + (size_t)n1 * 64);
        acc.x += v0.x + v1.x; acc.y += v0.y + v1.y;
        acc.z += v0.z + v1.z; acc.w += v0.w + v1.w;
    }
    for (; i < cnt; i += 2) {
        int idx = i + half;
        if (idx < cnt) {
            int n = g_sortA[base + idx];
            float4 v = *(const float4*)(xb + (size_t)n * 64);
            acc.x += v.x; acc.y += v.y; acc.z += v.z; acc.w += v.w;
        }
    }
    acc.x += __shfl_xor_sync(0xffffffffu, acc.x, 16);
    acc.y += __shfl_xor_sync(0xffffffffu, acc.y, 16);
    acc.z += __shfl_xor_sync(0xffffffffu, acc.z, 16);
    acc.w += __shfl_xor_sync(0xffffffffu, acc.w, 16);
    if (half == 0) {
        float s = (cnt > 0) ? 1.f / (float)cnt : 0.f;
        acc.x *= s; acc.y *= s; acc.z *= s; acc.w *= s;
        *(float4*)&g_aggA[((size_t)t * NH + h) * 64 + sub * 4] = acc;
    }
}

// ---------------- GEMM: efm = aggA @ Wcomb_t (fp16 out), PDL secondary ------
__global__ __launch_bounds__(256) void k_mma_ef() {
    __shared__ __align__(16) float As[128][32];
    __shared__ __align__(16) float Bs[2][64][32];
    int tid = threadIdx.x;
    int lane = tid & 31, warp = tid >> 5;
    int warpM = warp >> 1, warpN = warp & 1;
    int g = lane >> 2, t4 = lane & 3;
    int rot = (g & 3) << 3;
    int n0 = blockIdx.x * 128;
    int ty = blockIdx.y;

    // prologue (independent of gatherA): load both B chunks
    {
        const float4* src = (const float4*)&g_Bef[ty * 4096];
        float4* dst = (float4*)&Bs[0][0][0];
        for (int i = tid; i < 1024; i += 256) dst[i] = src[i];
    }
    cudaGridDependencySynchronize();   // wait for gatherA's aggA

    float acc[2][4][4] = {};
    for (int kc = 0; kc < 2; kc++) {
        __syncthreads();
        for (int i = tid; i < 4096; i += 256) {
            int m = i >> 5, kk = i & 31;
            int n = n0 + m;
            float v = (n < NH) ? g_aggA[((size_t)ty * NH + n) * 64 + kc * 32 + kk] : 0.f;
            As[m][swz(kk, m)] = to_tf32(v);
        }
        __syncthreads();
#pragma unroll
        for (int s = 0; s < 4; s++) {
            int pc = (s * 8 + 2 * t4 + rot) & 31;
            uint32_t a[2][4];
#pragma unroll
            for (int mt = 0; mt < 2; mt++) {
                int r = warpM * 32 + mt * 16 + g;
                float2 lo = *(const float2*)&As[r][pc];
                float2 hi = *(const float2*)&As[r + 8][pc];
                a[mt][0] = __float_as_uint(lo.x); a[mt][1] = __float_as_uint(hi.x);
                a[mt][2] = __float_as_uint(lo.y); a[mt][3] = __float_as_uint(hi.y);
            }
#pragma unroll
            for (int nt = 0; nt < 4; nt++) {
                int c = warpN * 32 + nt * 8 + g;
                float2 b = *(const float2*)&Bs[kc][c][pc];
                uint32_t b0 = __float_as_uint(b.x), b1 = __float_as_uint(b.y);
                mma_tf32(acc[0][nt], a[0], b0, b1);
                mma_tf32(acc[1][nt], a[1], b0, b1);
            }
        }
    }
#pragma unroll
    for (int mt = 0; mt < 2; mt++) {
        int r = n0 + warpM * 32 + mt * 16 + g;
#pragma unroll
        for (int nt = 0; nt < 4; nt++) {
            int c = warpN * 32 + nt * 8 + 2 * t4;
            if (r < NH)
                *(__half2*)&g_efmh[((size_t)ty * NH + r) * 64 + c] =
                    __floats2half2_rn(acc[mt][nt][0], acc[mt][nt][1]);
            if (r + 8 < NH)
                *(__half2*)&g_efmh[((size_t)ty * NH + r + 8) * 64 + c] =
                    __floats2half2_rn(acc[mt][nt][2], acc[mt][nt][3]);
        }
    }
}

// ---------------- gather B (PDL secondary): fp16 rows -----------------------
__global__ __launch_bounds__(256) void k_gatherB() {
    cudaTriggerProgrammaticLaunchCompletion();   // let k_gru prologue start
    int node = (blockIdx.x * 256 + threadIdx.x) >> 5;
    int lane = threadIdx.x & 31;
    int half = lane >> 4, sub = lane & 15;
    int base0 = 0, cnt0 = 0, base1 = 0, cnt1 = 0;
    if (node < NN) {                              // prologue
        base0 = g_offB[node * 2];     cnt0 = g_cntB[node * 2];
        base1 = g_offB[node * 2 + 1]; cnt1 = g_cntB[node * 2 + 1];
    }
    cudaGridDependencySynchronize();             // wait for k_mma_ef (g_efmh)
    if (node >= NN) return;
    const __half* eb = g_efmh + sub * 4;
    float4 tot = make_float4(0.f, 0.f, 0.f, 0.f);
#pragma unroll
    for (int t = 0; t < 2; t++) {
        int base = t ? base1 : base0;
        int cnt  = t ? cnt1 : cnt0;
        float4 acc = make_float4(0.f, 0.f, 0.f, 0.f);
        int i = 0;
        for (; i + 4 <= cnt; i += 4) {
            int o0 = g_sortB[base + i + half];
            int o1 = g_sortB[base + i + 2 + half];
            uint2 r0 = *(const uint2*)(eb + o0);
            uint2 r1 = *(const uint2*)(eb + o1);
            float2 f0 = __half22float2(*reinterpret_cast<__half2*>(&r0.x));
            float2 f1 = __half22float2(*reinterpret_cast<__half2*>(&r0.y));
            float2 f2 = __half22float2(*reinterpret_cast<__half2*>(&r1.x));
            float2 f3 = __half22float2(*reinterpret_cast<__half2*>(&r1.y));
            acc.x += f0.x + f2.x; acc.y += f0.y + f2.y;
            acc.z += f1.x + f3.x; acc.w += f1.y + f3.y;
        }
        for (; i < cnt; i += 2) {
            int idx = i + half;
            if (idx < cnt) {
                int o = g_sortB[base + idx];
                uint2 r0 = *(const uint2*)(eb + o);
                float2 f0 = __half22float2(*reinterpret_cast<__half2*>(&r0.x));
                float2 f1 = __half22float2(*reinterpret_cast<__half2*>(&r0.y));
                acc.x += f0.x; acc.y += f0.y; acc.z += f1.x; acc.w += f1.y;
            }
        }
        float s = (cnt > 0) ? 1.f / (float)cnt : 0.f;
        tot.x += acc.x * s; tot.y += acc.y * s;
        tot.z += acc.z * s; tot.w += acc.w * s;
    }
    tot.x += __shfl_xor_sync(0xffffffffu, tot.x, 16);
    tot.y += __shfl_xor_sync(0xffffffffu, tot.y, 16);
    tot.z += __shfl_xor_sync(0xffffffffu, tot.z, 16);
    tot.w += __shfl_xor_sync(0xffffffffu, tot.w, 16);
    if (half == 0) {
        float4 b = *(const float4*)&g_bcmix[sub * 4];
        float4 o;
        o.x = fmaxf(tot.x + b.x, 0.f); o.y = fmaxf(tot.y + b.y, 0.f);
        o.z = fmaxf(tot.z + b.z, 0.f); o.w = fmaxf(tot.w + b.w, 0.f);
        *(float4*)&g_h[(size_t)node * 64 + sub * 4] = o;
    }
}

// ---------------- persistent GRU: B-resident, PDL secondary -----------------
// Tail also resets counters for the next graph replay.
#define OF_AS   36864
#define OF_WRO  46080
#define OF_SRED 46336
#define OF_HS   46848
#define GRU_SMEM ((46848 + 8704) * 4)
__global__ __launch_bounds__(512) void k_gru(const float* __restrict__ h_prev,
                                             const float* __restrict__ Wro,
                                             const float* __restrict__ bro,
                                             float* __restrict__ out_h,
                                             float* __restrict__ out3) {
    extern __shared__ __align__(16) float sm[];
    uint32_t smb;
    asm("{ .reg .u64 t; cvta.to.shared.u64 t, %1; cvt.u32.u64 %0, t; }"
        : "=r"(smb) : "l"(sm));
    int tid = threadIdx.x;
    int lane = tid & 31, warp = tid >> 5;
    int warpM = warp >> 2, warpN = warp & 3;
    int g = lane >> 2, t = lane & 3;

    for (int i = tid; i < 9216; i += 512)
        cp16(smb + (uint32_t)i * 16, (const char*)g_Bgru + (size_t)i * 16);
    CP_COMMIT();
    if (tid < 256) {
        int j = tid >> 2, c = tid & 3;
        sm[OF_WRO + tid] = (c < 3) ? __ldg(&Wro[j * 64 + c]) : 0.f;
    }
    sm[OF_SRED + tid] = 0.f;
    float brd0 = __ldg(&bro[0]), brd1 = __ldg(&bro[1]), brd2 = __ldg(&bro[2]);

    cudaGridDependencySynchronize();   // wait for gatherB's g_h

#define STAGE_A(ptile, pkc) do {                                               \
        int _kc = (pkc);                                                       \
        uint32_t _dst = smb + (OF_AS + (_kc & 1) * 4608) * 4;                  \
        for (int i = tid; i < 1024; i += 512) {                                \
            int m = i >> 3, q = i & 7;                                         \
            int n = (ptile) * 128 + m;                                         \
            int nc = (n < NN) ? n : (NN - 1);                                  \
            const float* src = (_kc < 2)                                       \
                ? &g_h[(size_t)nc * 64 + _kc * 32 + q * 4]                     \
                : &h_prev[(size_t)nc * 64 + (_kc - 2) * 32 + q * 4];           \
            cp16(_dst + (uint32_t)(m * 144 + q * 16), src);                    \
        }                                                                      \
    } while (0)

    int tile = blockIdx.x;
    if (tile < NT) STAGE_A(tile, 0);
    CP_COMMIT();

    for (; tile < NT; tile += GRID_GRU) {
        int n0 = tile * 128;
        float acc[2][8][4] = {};
        for (int kc = 0; kc < 4; kc++) {
            CP_WAIT0();
            __syncthreads();
            if (kc < 3) { STAGE_A(tile, kc + 1); CP_COMMIT(); }
            const float* As = sm + OF_AS + (kc & 1) * 4608;
            const float* Bb = sm + kc * 9216;
#pragma unroll
            for (int s = 0; s < 4; s++) {
                int k0 = s * 8;
                uint32_t a[2][4];
#pragma unroll
                for (int mt = 0; mt < 2; mt++) {
                    int r = warpM * 32 + mt * 16 + g;
                    a[mt][0] = __float_as_uint(As[r * 36 + k0 + t]);
                    a[mt][1] = __float_as_uint(As[(r + 8) * 36 + k0 + t]);
                    a[mt][2] = __float_as_uint(As[r * 36 + k0 + t + 4]);
                    a[mt][3] = __float_as_uint(As[(r + 8) * 36 + k0 + t + 4]);
                }
#pragma unroll
                for (int nt = 0; nt < 8; nt++) {
                    int c = warpN * 64 + nt * 8 + g;
                    float2 bb = *(const float2*)&Bb[c * 36 + k0 + 2 * t];
                    mma_tf32(acc[0][nt], a[0],
                             __float_as_uint(bb.x), __float_as_uint(bb.y));
                    mma_tf32(acc[1][nt], a[1],
                             __float_as_uint(bb.x), __float_as_uint(bb.y));
                }
            }
        }

        // ---- gate epilogue: hp from As bufs (h_prev resident), hn -> Hs ----
        const float* Ab0 = sm + OF_AS;
        const float* Ab1 = sm + OF_AS + 4608;
        float p[2][2][3] = {};
        bool even = (t & 1) == 0;
#pragma unroll
        for (int mt = 0; mt < 2; mt++) {
#pragma unroll
            for (int nt = 0; nt < 8; nt++) {
                int j = warpN * 16 + nt * 2 + (t >> 1);
                float br = g_bias[j], bz = g_bias[64 + j];
                float bn = g_bias[128 + j], bh = g_bias[192 + j];
                float w0 = sm[OF_WRO + j * 4 + 0];
                float w1 = sm[OF_WRO + j * 4 + 1];
                float w2 = sm[OF_WRO + j * 4 + 2];
#pragma unroll
                for (int rh = 0; rh < 2; rh++) {
                    int m = warpM * 32 + mt * 16 + rh * 8 + g;
                    float v0 = acc[mt][nt][rh * 2 + 0];
                    float v1 = acc[mt][nt][rh * 2 + 1];
                    float o0 = __shfl_xor_sync(0xffffffffu, v0, 1);
                    float o1 = __shfl_xor_sync(0xffffffffu, v1, 1);
                    float hn = 0.f;
                    if (even) {
                        float r_ = sigf(v0 + br);
                        float z_ = sigf(v1 + bz);
                        float nv = tanh_fast((o0 + bn) + r_ * (o1 + bh));
                        float hp = (j < 32) ? Ab0[m * 36 + j] : Ab1[m * 36 + j - 32];
                        hn = (1.f - z_) * nv + z_ * hp;
                        sm[OF_HS + m * 68 + j] = hn;
                    }
                    p[mt][rh][0] += hn * w0;
                    p[mt][rh][1] += hn * w1;
                    p[mt][rh][2] += hn * w2;
                }
            }
        }
#pragma unroll
        for (int mt = 0; mt < 2; mt++)
#pragma unroll
            for (int rh = 0; rh < 2; rh++)
#pragma unroll
                for (int c = 0; c < 3; c++) {
                    float v = p[mt][rh][c] + __shfl_xor_sync(0xffffffffu, p[mt][rh][c], 2);
                    if (t == 0)
                        atomicAdd(&sm[OF_SRED + (warpM * 32 + mt * 16 + rh * 8 + g) * 4 + c], v);
                }
        __syncthreads();

        {
            int pt = tile + GRID_GRU;
            if (pt < NT) { STAGE_A(pt, 0); CP_COMMIT(); }
        }

        for (int i = tid; i < 2048; i += 512) {
            int m = i >> 4, q = i & 15;
            int n = n0 + m;
            if (n < NN)
                *(float4*)&out_h[(size_t)n * 64 + q * 4] =
                    *(const float4*)&sm[OF_HS + m * 68 + q * 4];
        }
        {
            int nd = tid >> 2, c = tid & 3;
            int n = n0 + nd;
            if (c < 3 && n < NN)
                out3[(size_t)n * 3 + c] = sm[OF_SRED + tid] +
                                          (c == 0 ? brd0 : (c == 1 ? brd1 : brd2));
        }
        __syncthreads();
        sm[OF_SRED + tid] = 0.f;
    }
#undef STAGE_A

    // ---- reset counters for next run (nothing reads them after this point) --
    {
        int gstride = GRID_GRU * 512;
        int gtid = blockIdx.x * 512 + tid;
        for (int i = gtid; i < NKA; i += gstride) g_cntA[i] = 0;
        for (int i = gtid; i < NKB; i += gstride) g_cntB[i] = 0;
        if (gtid == 0) { g_baseA = 0; g_baseB = 0; }
    }
}

// ---------------- launch -----------------------------------------------------
extern "C" void kernel_launch(void* const* d_in, const int* in_sizes, int n_in,
                              void* d_out, int out_size) {
    const float* x       = (const float*)d_in[0];
    const float* h_prev  = (const float*)d_in[1];
    const int* node_idx  = (const int*)d_in[2];
    const int* hedge_idx = (const int*)d_in[3];
    const int* edge_attr = (const int*)d_in[4];
    const float* W_conv  = (const float*)d_in[5];
    const float* b_conv  = (const float*)d_in[6];
    const float* W_mix   = (const float*)d_in[7];
    const float* b_mix   = (const float*)d_in[8];
    const float* W_ih    = (const float*)d_in[9];
    const float* W_hh    = (const float*)d_in[10];
    const float* b_ih    = (const float*)d_in[11];
    const float* b_hh    = (const float*)d_in[12];
    const float* W_ro    = (const float*)d_in[13];
    const float* b_ro    = (const float*)d_in[14];

    float* h_next = (float*)d_out;
    float* out3   = (float*)d_out + (size_t)NN * 64;

    cudaFuncSetAttribute(k_gru, cudaFuncAttributeMaxDynamicSharedMemorySize, GRU_SMEM);

    cudaLaunchAttribute pdl[1];
    pdl[0].id = cudaLaunchAttributeProgrammaticStreamSerialization;
    pdl[0].val.programmaticStreamSerializationAllowed = 1;

    k_prep_hist<<<(NE4 + 255) / 256, 256>>>(W_conv, W_mix, b_mix, b_conv,
                                            W_ih, W_hh, b_ih, b_hh,
                                            node_idx, hedge_idx, edge_attr);
    k_offsets<<<NBA + NBB, 1024>>>();
    {
        cudaLaunchConfig_t cfg = {};
        cfg.gridDim = dim3((NE4 + 255) / 256);
        cfg.blockDim = dim3(256);
        cfg.attrs = pdl; cfg.numAttrs = 1;
        cudaLaunchKernelEx(&cfg, k_perm, node_idx, hedge_idx, edge_attr);
    }
    {
        cudaLaunchConfig_t cfg = {};
        cfg.gridDim = dim3((NKA * 32 + 255) / 256);
        cfg.blockDim = dim3(256);
        cfg.attrs = pdl; cfg.numAttrs = 1;
        cudaLaunchKernelEx(&cfg, k_gatherA, x);
    }
    {
        cudaLaunchConfig_t cfg = {};
        cfg.gridDim = dim3((NH + 127) / 128, 2);
        cfg.blockDim = dim3(256);
        cfg.attrs = pdl; cfg.numAttrs = 1;
        cudaLaunchKernelEx(&cfg, k_mma_ef);
    }
    {
        cudaLaunchConfig_t cfg = {};
        cfg.gridDim = dim3((NN * 32 + 255) / 256);
        cfg.blockDim = dim3(256);
        cfg.attrs = pdl; cfg.numAttrs = 1;
        cudaLaunchKernelEx(&cfg, k_gatherB);
    }
    {
        cudaLaunchConfig_t cfg = {};
        cfg.gridDim = dim3(GRID_GRU);
        cfg.blockDim = dim3(512);
        cfg.dynamicSmemBytes = GRU_SMEM;
        cfg.attrs = pdl; cfg.numAttrs = 1;
        cudaLaunchKernelEx(&cfg, k_gru, h_prev, W_ro, b_ro, h_next, out3);
    }
}

// round 17
// speedup vs baseline: 1.0247x; 1.0094x over previous
#include <cuda_runtime.h>
#include <cuda_fp16.h>
#include <cstdint>

#define NN 100000
#define NH 20000
#define NE 800000
#define NE4 (NE/4)
#define NKA (NH*2)     // hedge-type keys
#define NKB (NN*2)     // node-type keys
#define NBA ((NKA + 1023) / 1024)
#define NBB ((NKB + 1023) / 1024)
#define NT  ((NN + 127) / 128)   // 782 GRU tiles
#define GRID_GRU 152

// ---------------- static device buffers (zero-init at load) -----------------
__device__ __align__(16) float g_aggA[(size_t)2*NH*64];   // (Σx)/cnt per (t,h)
__device__ __align__(16) __half g_efmh[(size_t)2*NH*64];  // aggA @ Wcomb_t (fp16)
__device__ __align__(16) float g_h[(size_t)NN*64];        // relu(mix)
__device__ int g_cntA[NKA], g_offA[NKA];
__device__ int g_cntB[NKB], g_offB[NKB];
__device__ int g_baseA, g_baseB;
__device__ __align__(16) int g_rankA[NE], g_rankB[NE];
__device__ int g_sortA[NE];   // node ids, sorted by (hedge,type)
__device__ int g_sortB[NE];   // efm element offsets, sorted by (node,type)
// B images
__device__ __align__(16) float g_Bef[2*2*64*32];        // Wcomb_t (swizzled, tf32)
__device__ __align__(16) float g_Bgru[4*256*36];        // GRU B, pitch-36, pair-permuted k
__device__ float g_bias[256];
__device__ float g_bcmix[64];

// ---------------- helpers ---------------------------------------------------
__device__ __forceinline__ float to_tf32(float v) {
    uint32_t u; asm("cvt.rna.tf32.f32 %0, %1;" : "=r"(u) : "f"(v));
    return __uint_as_float(u);
}
__device__ __forceinline__ int swz(int kk, int row) {
    int r = kk & 7;
    int pos = (r < 4) ? (r * 2) : ((r - 4) * 2 + 1);
    int sc = (kk & 24) + pos;
    return (sc + ((row & 3) << 3)) & 31;
}
__device__ __forceinline__ void mma_tf32(float* c, const uint32_t* a,
                                         uint32_t b0, uint32_t b1) {
    asm volatile(
        "mma.sync.aligned.m16n8k8.row.col.f32.tf32.tf32.f32 "
        "{%0,%1,%2,%3}, {%4,%5,%6,%7}, {%8,%9}, {%0,%1,%2,%3};"
        : "+f"(c[0]), "+f"(c[1]), "+f"(c[2]), "+f"(c[3])
        : "r"(a[0]), "r"(a[1]), "r"(a[2]), "r"(a[3]), "r"(b0), "r"(b1));
}
__device__ __forceinline__ float sigf(float x) { return 1.f / (1.f + __expf(-x)); }
__device__ __forceinline__ float tanh_fast(float x) {
    return 1.f - 2.f / (__expf(2.f * x) + 1.f);
}
__device__ __forceinline__ void cp16(uint32_t dst, const void* src) {
    asm volatile("cp.async.cg.shared.global [%0], [%1], 16;" :: "r"(dst), "l"(src));
}
#define CP_COMMIT() asm volatile("cp.async.commit_group;" ::: "memory")
#define CP_WAIT0()  asm volatile("cp.async.wait_group 0;" ::: "memory")

// ---------------- merged prep + histogram (counters zeroed by prior gru) ----
__global__ void k_prep_hist(const float* __restrict__ Wc, const float* __restrict__ Wmix,
                            const float* __restrict__ bmix, const float* __restrict__ bconv,
                            const float* __restrict__ Wih, const float* __restrict__ Whh,
                            const float* __restrict__ bih, const float* __restrict__ bhh,
                            const int* __restrict__ ni, const int* __restrict__ hi,
                            const int* __restrict__ ea) {
    int idx = blockIdx.x * blockDim.x + threadIdx.x;

    if (idx < 8192) {                     // Bef: [2][2 kc][64 c][32] (swizzled)
        int t = idx >> 12, rem = idx & 4095;
        int kc = rem >> 11, rem2 = rem & 2047, c = rem2 >> 5, kk = rem2 & 31;
        int k = kc * 32 + kk;
        float s = 0.f;
        const float* wr = Wc + t * 4096 + k * 64;
        const float* wm = Wmix + (size_t)t * 64 * 64 + c;
#pragma unroll 8
        for (int m = 0; m < 64; m++) s += wr[m] * wm[(size_t)m * 64];
        g_Bef[((t * 2 + kc) * 64 + c) * 32 + swz(kk, c)] = to_tf32(s);
    } else if (idx < 8192 + 36864) {      // Bgru: [4 kc][256 c][36], pair-permuted k
        int i = idx - 8192;
        int kc = i / 9216, rem = i - kc * 9216;
        int c = rem / 36, kkp = rem - c * 36;
        float v = 0.f;
        if (kkp < 32) {
            int k0 = kkp & ~7, r = kkp & 7;
            int kk = k0 + (r >> 1) + ((r & 1) ? 4 : 0);
            int k = kc * 32 + kk;
            int j = c >> 2, seg = c & 3;
            if (k < 64) {
                if (seg == 0)      v = Wih[k * 192 + j];
                else if (seg == 1) v = Wih[k * 192 + 64 + j];
                else if (seg == 2) v = Wih[k * 192 + 128 + j];
            } else {
                int k2 = k - 64;
                if (seg == 0)      v = Whh[k2 * 192 + j];
                else if (seg == 1) v = Whh[k2 * 192 + 64 + j];
                else if (seg == 3) v = Whh[k2 * 192 + 128 + j];
            }
        }
        g_Bgru[i] = to_tf32(v);
    } else if (idx < 45056 + 256) {       // GRU bias (seg-major)
        int c = idx - 45056;
        int seg = c >> 6, j = c & 63;
        float b;
        if (seg == 0)      b = bih[j] + bhh[j];
        else if (seg == 1) b = bih[64 + j] + bhh[64 + j];
        else if (seg == 2) b = bih[128 + j];
        else               b = bhh[128 + j];
        g_bias[c] = b;
    } else if (idx < 45056 + 256 + 64) {  // folded mix bias
        int j = idx - 45056 - 256;
        float s = bmix[j];
        for (int k = 0; k < 128; k++) s += bconv[k] * Wmix[k * 64 + j];
        g_bcmix[j] = s;
    }

    // ---- histogram + rank capture (4 edges/thread) ----
    if (idx < NE4) {
        int4 n = ((const int4*)ni)[idx];
        int4 h = ((const int4*)hi)[idx];
        int4 t = ((const int4*)ea)[idx];
        int4 ra, rb;
        ra.x = atomicAdd(&g_cntA[h.x * 2 + t.x], 1);
        ra.y = atomicAdd(&g_cntA[h.y * 2 + t.y], 1);
        ra.z = atomicAdd(&g_cntA[h.z * 2 + t.z], 1);
        ra.w = atomicAdd(&g_cntA[h.w * 2 + t.w], 1);
        rb.x = atomicAdd(&g_cntB[n.x * 2 + t.x], 1);
        rb.y = atomicAdd(&g_cntB[n.y * 2 + t.y], 1);
        rb.z = atomicAdd(&g_cntB[n.z * 2 + t.z], 1);
        rb.w = atomicAdd(&g_cntB[n.w * 2 + t.w], 1);
        ((int4*)g_rankA)[idx] = ra;
        ((int4*)g_rankB)[idx] = rb;
    }
}

// ---------------- parallel offsets: block scan + atomic range claim ---------
__global__ __launch_bounds__(1024) void k_offsets() {
    cudaTriggerProgrammaticLaunchCompletion();   // let k_perm prologue start
    __shared__ int sm[1024];
    __shared__ int blockBase;
    int b = blockIdx.x;
    const int* cnt; int* off; int n; int* gbase;
    if (b < NBA) { cnt = g_cntA; off = g_offA; n = NKA; gbase = &g_baseA; }
    else { b -= NBA; cnt = g_cntB; off = g_offB; n = NKB; gbase = &g_baseB; }
    int tid = threadIdx.x;
    int i = b * 1024 + tid;
    int v = (i < n) ? cnt[i] : 0;
    sm[tid] = v;
    __syncthreads();
    for (int d = 1; d < 1024; d <<= 1) {
        int t = (tid >= d) ? sm[tid - d] : 0;
        __syncthreads();
        sm[tid] += t;
        __syncthreads();
    }
    if (tid == 1023) blockBase = atomicAdd(gbase, sm[1023]);
    __syncthreads();
    if (i < n) off[i] = blockBase + sm[tid] - v;
}

// ---------------- permute (PDL secondary): prologue loads, then scatter -----
__global__ void k_perm(const int* __restrict__ ni, const int* __restrict__ hi,
                       const int* __restrict__ ea) {
    cudaTriggerProgrammaticLaunchCompletion();   // let k_gatherA prologue start
    int i = blockIdx.x * 256 + threadIdx.x;
    int4 n = {}, h = {}, t = {}, ra = {}, rb = {};
    if (i < NE4) {
        n = ((const int4*)ni)[i];
        h = ((const int4*)hi)[i];
        t = ((const int4*)ea)[i];
        ra = ((const int4*)g_rankA)[i];
        rb = ((const int4*)g_rankB)[i];
    }
    cudaGridDependencySynchronize();             // wait for k_offsets (g_off*)
    if (i >= NE4) return;
    g_sortA[g_offA[h.x * 2 + t.x] + ra.x] = n.x;
    g_sortA[g_offA[h.y * 2 + t.y] + ra.y] = n.y;
    g_sortA[g_offA[h.z * 2 + t.z] + ra.z] = n.z;
    g_sortA[g_offA[h.w * 2 + t.w] + ra.w] = n.w;
    g_sortB[g_offB[n.x * 2 + t.x] + rb.x] = (t.x * NH + h.x) * 64;
    g_sortB[g_offB[n.y * 2 + t.y] + rb.y] = (t.y * NH + h.y) * 64;
    g_sortB[g_offB[n.z * 2 + t.z] + rb.z] = (t.z * NH + h.z) * 64;
    g_sortB[g_offB[n.w * 2 + t.w] + rb.w] = (t.w * NH + h.w) * 64;
}

// ---------------- gather A (PDL secondary): 8-row unrolled, fp32 x ----------
__global__ __launch_bounds__(256) void k_gatherA(const float* __restrict__ x) {
    cudaTriggerProgrammaticLaunchCompletion();   // let k_mma_ef prologue start
    int key = (blockIdx.x * 256 + threadIdx.x) >> 5;
    int lane = threadIdx.x & 31;
    int half = lane >> 4, sub = lane & 15;
    int base = 0, cnt = 0;
    if (key < NKA) { base = g_offA[key]; cnt = g_cntA[key]; }  // prologue
    cudaGridDependencySynchronize();             // wait for k_perm (g_sortA)
    if (key >= NKA) return;
    int t = key & 1, h = key >> 1;
    const float* xb = x + sub * 4;
    float4 acc = make_float4(0.f, 0.f, 0.f, 0.f);
    int i = 0;
    for (; i + 8 <= cnt; i += 8) {
        // 4 independent idx->row chains in flight
        int n0 = g_sortA[base + i + half];
        int n1 = g_sortA[base + i + 2 + half];
        int n2 = g_sortA[base + i + 4 + half];
        int n3 = g_sortA[base + i + 6 + half];
        float4 v0 = *(const float4*)(xb + (size_t)n0 * 64);
        float4 v1 = *(const float4*)(xb + (size_t)n1 * 64);
        float4 v2 = *(const float4*)(xb + (size_t)n2 * 64);
        float4 v3 = *(const float4*)(xb + (size_t)n3 * 64);
        acc.x += v0.x; acc.y += v0.y; acc.z += v0.z; acc.w += v0.w;
        acc.x += v1.x; acc.y += v1.y; acc.z += v1.z; acc.w += v1.w;
        acc.x += v2.x; acc.y += v2.y; acc.z += v2.z; acc.w += v2.w;
        acc.x += v3.x; acc.y += v3.y; acc.z += v3.z; acc.w += v3.w;
    }
    for (; i < cnt; i += 2) {
        int idx = i + half;
        if (idx < cnt) {
            int n = g_sortA[base + idx];
            float4 v = *(const float4*)(xb + (size_t)n * 64);
            acc.x += v.x; acc.y += v.y; acc.z += v.z; acc.w += v.w;
        }
    }
    acc.x += __shfl_xor_sync(0xffffffffu, acc.x, 16);
    acc.y += __shfl_xor_sync(0xffffffffu, acc.y, 16);
    acc.z += __shfl_xor_sync(0xffffffffu, acc.z, 16);
    acc.w += __shfl_xor_sync(0xffffffffu, acc.w, 16);
    if (half == 0) {
        float s = (cnt > 0) ? 1.f / (float)cnt : 0.f;
        acc.x *= s; acc.y *= s; acc.z *= s; acc.w *= s;
        *(float4*)&g_aggA[((size_t)t * NH + h) * 64 + sub * 4] = acc;
    }
}

// ---------------- GEMM: efm = aggA @ Wcomb_t (fp16 out), PDL secondary ------
__global__ __launch_bounds__(256) void k_mma_ef() {
    __shared__ __align__(16) float As[128][32];
    __shared__ __align__(16) float Bs[2][64][32];
    int tid = threadIdx.x;
    int lane = tid & 31, warp = tid >> 5;
    int warpM = warp >> 1, warpN = warp & 1;
    int g = lane >> 2, t4 = lane & 3;
    int rot = (g & 3) << 3;
    int n0 = blockIdx.x * 128;
    int ty = blockIdx.y;

    // prologue (independent of gatherA): load both B chunks
    {
        const float4* src = (const float4*)&g_Bef[ty * 4096];
        float4* dst = (float4*)&Bs[0][0][0];
        for (int i = tid; i < 1024; i += 256) dst[i] = src[i];
    }
    cudaGridDependencySynchronize();   // wait for gatherA's aggA

    float acc[2][4][4] = {};
    for (int kc = 0; kc < 2; kc++) {
        __syncthreads();
        for (int i = tid; i < 4096; i += 256) {
            int m = i >> 5, kk = i & 31;
            int n = n0 + m;
            float v = (n < NH) ? g_aggA[((size_t)ty * NH + n) * 64 + kc * 32 + kk] : 0.f;
            As[m][swz(kk, m)] = to_tf32(v);
        }
        __syncthreads();
#pragma unroll
        for (int s = 0; s < 4; s++) {
            int pc = (s * 8 + 2 * t4 + rot) & 31;
            uint32_t a[2][4];
#pragma unroll
            for (int mt = 0; mt < 2; mt++) {
                int r = warpM * 32 + mt * 16 + g;
                float2 lo = *(const float2*)&As[r][pc];
                float2 hi = *(const float2*)&As[r + 8][pc];
                a[mt][0] = __float_as_uint(lo.x); a[mt][1] = __float_as_uint(hi.x);
                a[mt][2] = __float_as_uint(lo.y); a[mt][3] = __float_as_uint(hi.y);
            }
#pragma unroll
            for (int nt = 0; nt < 4; nt++) {
                int c = warpN * 32 + nt * 8 + g;
                float2 b = *(const float2*)&Bs[kc][c][pc];
                uint32_t b0 = __float_as_uint(b.x), b1 = __float_as_uint(b.y);
                mma_tf32(acc[0][nt], a[0], b0, b1);
                mma_tf32(acc[1][nt], a[1], b0, b1);
            }
        }
    }
#pragma unroll
    for (int mt = 0; mt < 2; mt++) {
        int r = n0 + warpM * 32 + mt * 16 + g;
#pragma unroll
        for (int nt = 0; nt < 4; nt++) {
            int c = warpN * 32 + nt * 8 + 2 * t4;
            if (r < NH)
                *(__half2*)&g_efmh[((size_t)ty * NH + r) * 64 + c] =
                    __floats2half2_rn(acc[mt][nt][0], acc[mt][nt][1]);
            if (r + 8 < NH)
                *(__half2*)&g_efmh[((size_t)ty * NH + r + 8) * 64 + c] =
                    __floats2half2_rn(acc[mt][nt][2], acc[mt][nt][3]);
        }
    }
}

// ---------------- gather B (PDL secondary): 8-row unrolled, fp16 rows -------
__global__ __launch_bounds__(256) void k_gatherB() {
    cudaTriggerProgrammaticLaunchCompletion();   // let k_gru prologue start
    int node = (blockIdx.x * 256 + threadIdx.x) >> 5;
    int lane = threadIdx.x & 31;
    int half = lane >> 4, sub = lane & 15;
    int base0 = 0, cnt0 = 0, base1 = 0, cnt1 = 0;
    if (node < NN) {                              // prologue
        base0 = g_offB[node * 2];     cnt0 = g_cntB[node * 2];
        base1 = g_offB[node * 2 + 1]; cnt1 = g_cntB[node * 2 + 1];
    }
    cudaGridDependencySynchronize();             // wait for k_mma_ef (g_efmh)
    if (node >= NN) return;
    const __half* eb = g_efmh + sub * 4;
    float4 tot = make_float4(0.f, 0.f, 0.f, 0.f);
#pragma unroll
    for (int t = 0; t < 2; t++) {
        int base = t ? base1 : base0;
        int cnt  = t ? cnt1 : cnt0;
        float4 acc = make_float4(0.f, 0.f, 0.f, 0.f);
        int i = 0;
        for (; i + 8 <= cnt; i += 8) {
            int o0 = g_sortB[base + i + half];
            int o1 = g_sortB[base + i + 2 + half];
            int o2 = g_sortB[base + i + 4 + half];
            int o3 = g_sortB[base + i + 6 + half];
            uint2 r0 = *(const uint2*)(eb + o0);
            uint2 r1 = *(const uint2*)(eb + o1);
            uint2 r2 = *(const uint2*)(eb + o2);
            uint2 r3 = *(const uint2*)(eb + o3);
            float2 a0 = __half22float2(*reinterpret_cast<__half2*>(&r0.x));
            float2 a1 = __half22float2(*reinterpret_cast<__half2*>(&r0.y));
            float2 b0 = __half22float2(*reinterpret_cast<__half2*>(&r1.x));
            float2 b1 = __half22float2(*reinterpret_cast<__half2*>(&r1.y));
            float2 c0 = __half22float2(*reinterpret_cast<__half2*>(&r2.x));
            float2 c1 = __half22float2(*reinterpret_cast<__half2*>(&r2.y));
            float2 d0 = __half22float2(*reinterpret_cast<__half2*>(&r3.x));
            float2 d1 = __half22float2(*reinterpret_cast<__half2*>(&r3.y));
            acc.x += a0.x; acc.y += a0.y; acc.z += a1.x; acc.w += a1.y;
            acc.x += b0.x; acc.y += b0.y; acc.z += b1.x; acc.w += b1.y;
            acc.x += c0.x; acc.y += c0.y; acc.z += c1.x; acc.w += c1.y;
            acc.x += d0.x; acc.y += d0.y; acc.z += d1.x; acc.w += d1.y;
        }
        for (; i < cnt; i += 2) {
            int idx = i + half;
            if (idx < cnt) {
                int o = g_sortB[base + idx];
                uint2 r0 = *(const uint2*)(eb + o);
                float2 f0 = __half22float2(*reinterpret_cast<__half2*>(&r0.x));
                float2 f1 = __half22float2(*reinterpret_cast<__half2*>(&r0.y));
                acc.x += f0.x; acc.y += f0.y; acc.z += f1.x; acc.w += f1.y;
            }
        }
        float s = (cnt > 0) ? 1.f / (float)cnt : 0.f;
        tot.x += acc.x * s; tot.y += acc.y * s;
        tot.z += acc.z * s; tot.w += acc.w * s;
    }
    tot.x += __shfl_xor_sync(0xffffffffu, tot.x, 16);
    tot.y += __shfl_xor_sync(0xffffffffu, tot.y, 16);
    tot.z += __shfl_xor_sync(0xffffffffu, tot.z, 16);
    tot.w += __shfl_xor_sync(0xffffffffu, tot.w, 16);
    if (half == 0) {
        float4 b = *(const float4*)&g_bcmix[sub * 4];
        float4 o;
        o.x = fmaxf(tot.x + b.x, 0.f); o.y = fmaxf(tot.y + b.y, 0.f);
        o.z = fmaxf(tot.z + b.z, 0.f); o.w = fmaxf(tot.w + b.w, 0.f);
        *(float4*)&g_h[(size_t)node * 64 + sub * 4] = o;
    }
}

// ---------------- persistent GRU: B-resident, PDL secondary -----------------
// Tail also resets counters for the next graph replay.
#define OF_AS   36864
#define OF_WRO  46080
#define OF_SRED 46336
#define OF_HS   46848
#define GRU_SMEM ((46848 + 8704) * 4)
__global__ __launch_bounds__(512) void k_gru(const float* __restrict__ h_prev,
                                             const float* __restrict__ Wro,
                                             const float* __restrict__ bro,
                                             float* __restrict__ out_h,
                                             float* __restrict__ out3) {
    extern __shared__ __align__(16) float sm[];
    uint32_t smb;
    asm("{ .reg .u64 t; cvta.to.shared.u64 t, %1; cvt.u32.u64 %0, t; }"
        : "=r"(smb) : "l"(sm));
    int tid = threadIdx.x;
    int lane = tid & 31, warp = tid >> 5;
    int warpM = warp >> 2, warpN = warp & 3;
    int g = lane >> 2, t = lane & 3;

    for (int i = tid; i < 9216; i += 512)
        cp16(smb + (uint32_t)i * 16, (const char*)g_Bgru + (size_t)i * 16);
    CP_COMMIT();
    if (tid < 256) {
        int j = tid >> 2, c = tid & 3;
        sm[OF_WRO + tid] = (c < 3) ? __ldg(&Wro[j * 64 + c]) : 0.f;
    }
    sm[OF_SRED + tid] = 0.f;
    float brd0 = __ldg(&bro[0]), brd1 = __ldg(&bro[1]), brd2 = __ldg(&bro[2]);

    cudaGridDependencySynchronize();   // wait for gatherB's g_h

#define STAGE_A(ptile, pkc) do {                                               \
        int _kc = (pkc);                                                       \
        uint32_t _dst = smb + (OF_AS + (_kc & 1) * 4608) * 4;                  \
        for (int i = tid; i < 1024; i += 512) {                                \
            int m = i >> 3, q = i & 7;                                         \
            int n = (ptile) * 128 + m;                                         \
            int nc = (n < NN) ? n : (NN - 1);                                  \
            const float* src = (_kc < 2)                                       \
                ? &g_h[(size_t)nc * 64 + _kc * 32 + q * 4]                     \
                : &h_prev[(size_t)nc * 64 + (_kc - 2) * 32 + q * 4];           \
            cp16(_dst + (uint32_t)(m * 144 + q * 16), src);                    \
        }                                                                      \
    } while (0)

    int tile = blockIdx.x;
    if (tile < NT) STAGE_A(tile, 0);
    CP_COMMIT();

    for (; tile < NT; tile += GRID_GRU) {
        int n0 = tile * 128;
        float acc[2][8][4] = {};
        for (int kc = 0; kc < 4; kc++) {
            CP_WAIT0();
            __syncthreads();
            if (kc < 3) { STAGE_A(tile, kc + 1); CP_COMMIT(); }
            const float* As = sm + OF_AS + (kc & 1) * 4608;
            const float* Bb = sm + kc * 9216;
#pragma unroll
            for (int s = 0; s < 4; s++) {
                int k0 = s * 8;
                uint32_t a[2][4];
#pragma unroll
                for (int mt = 0; mt < 2; mt++) {
                    int r = warpM * 32 + mt * 16 + g;
                    a[mt][0] = __float_as_uint(As[r * 36 + k0 + t]);
                    a[mt][1] = __float_as_uint(As[(r + 8) * 36 + k0 + t]);
                    a[mt][2] = __float_as_uint(As[r * 36 + k0 + t + 4]);
                    a[mt][3] = __float_as_uint(As[(r + 8) * 36 + k0 + t + 4]);
                }
#pragma unroll
                for (int nt = 0; nt < 8; nt++) {
                    int c = warpN * 64 + nt * 8 + g;
                    float2 bb = *(const float2*)&Bb[c * 36 + k0 + 2 * t];
                    mma_tf32(acc[0][nt], a[0],
                             __float_as_uint(bb.x), __float_as_uint(bb.y));
                    mma_tf32(acc[1][nt], a[1],
                             __float_as_uint(bb.x), __float_as_uint(bb.y));
                }
            }
        }

        // ---- gate epilogue: hp from As bufs (h_prev resident), hn -> Hs ----
        const float* Ab0 = sm + OF_AS;
        const float* Ab1 = sm + OF_AS + 4608;
        float p[2][2][3] = {};
        bool even = (t & 1) == 0;
#pragma unroll
        for (int mt = 0; mt < 2; mt++) {
#pragma unroll
            for (int nt = 0; nt < 8; nt++) {
                int j = warpN * 16 + nt * 2 + (t >> 1);
                float br = g_bias[j], bz = g_bias[64 + j];
                float bn = g_bias[128 + j], bh = g_bias[192 + j];
                float w0 = sm[OF_WRO + j * 4 + 0];
                float w1 = sm[OF_WRO + j * 4 + 1];
                float w2 = sm[OF_WRO + j * 4 + 2];
#pragma unroll
                for (int rh = 0; rh < 2; rh++) {
                    int m = warpM * 32 + mt * 16 + rh * 8 + g;
                    float v0 = acc[mt][nt][rh * 2 + 0];
                    float v1 = acc[mt][nt][rh * 2 + 1];
                    float o0 = __shfl_xor_sync(0xffffffffu, v0, 1);
                    float o1 = __shfl_xor_sync(0xffffffffu, v1, 1);
                    float hn = 0.f;
                    if (even) {
                        float r_ = sigf(v0 + br);
                        float z_ = sigf(v1 + bz);
                        float nv = tanh_fast((o0 + bn) + r_ * (o1 + bh));
                        float hp = (j < 32) ? Ab0[m * 36 + j] : Ab1[m * 36 + j - 32];
                        hn = (1.f - z_) * nv + z_ * hp;
                        sm[OF_HS + m * 68 + j] = hn;
                    }
                    p[mt][rh][0] += hn * w0;
                    p[mt][rh][1] += hn * w1;
                    p[mt][rh][2] += hn * w2;
                }
            }
        }
#pragma unroll
        for (int mt = 0; mt < 2; mt++)
#pragma unroll
            for (int rh = 0; rh < 2; rh++)
#pragma unroll
                for (int c = 0; c < 3; c++) {
                    float v = p[mt][rh][c] + __shfl_xor_sync(0xffffffffu, p[mt][rh][c], 2);
                    if (t == 0)
                        atomicAdd(&sm[OF_SRED + (warpM * 32 + mt * 16 + rh * 8 + g) * 4 + c], v);
                }
        __syncthreads();

        {
            int pt = tile + GRID_GRU;
            if (pt < NT) { STAGE_A(pt, 0); CP_COMMIT(); }
        }

        for (int i = tid; i < 2048; i += 512) {
            int m = i >> 4, q = i & 15;
            int n = n0 + m;
            if (n < NN)
                *(float4*)&out_h[(size_t)n * 64 + q * 4] =
                    *(const float4*)&sm[OF_HS + m * 68 + q * 4];
        }
        {
            int nd = tid >> 2, c = tid & 3;
            int n = n0 + nd;
            if (c < 3 && n < NN)
                out3[(size_t)n * 3 + c] = sm[OF_SRED + tid] +
                                          (c == 0 ? brd0 : (c == 1 ? brd1 : brd2));
        }
        __syncthreads();
        sm[OF_SRED + tid] = 0.f;
    }
#undef STAGE_A

    // ---- reset counters for next run (nothing reads them after this point) --
    {
        int gstride = GRID_GRU * 512;
        int gtid = blockIdx.x * 512 + tid;
        for (int i = gtid; i < NKA; i += gstride) g_cntA[i] = 0;
        for (int i = gtid; i < NKB; i += gstride) g_cntB[i] = 0;
        if (gtid == 0) { g_baseA = 0; g_baseB = 0; }
    }
}

// ---------------- launch -----------------------------------------------------
extern "C" void kernel_launch(void* const* d_in, const int* in_sizes, int n_in,
                              void* d_out, int out_size) {
    const float* x       = (const float*)d_in[0];
    const float* h_prev  = (const float*)d_in[1];
    const int* node_idx  = (const int*)d_in[2];
    const int* hedge_idx = (const int*)d_in[3];
    const int* edge_attr = (const int*)d_in[4];
    const float* W_conv  = (const float*)d_in[5];
    const float* b_conv  = (const float*)d_in[6];
    const float* W_mix   = (const float*)d_in[7];
    const float* b_mix   = (const float*)d_in[8];
    const float* W_ih    = (const float*)d_in[9];
    const float* W_hh    = (const float*)d_in[10];
    const float* b_ih    = (const float*)d_in[11];
    const float* b_hh    = (const float*)d_in[12];
    const float* W_ro    = (const float*)d_in[13];
    const float* b_ro    = (const float*)d_in[14];

    float* h_next = (float*)d_out;
    float* out3   = (float*)d_out + (size_t)NN * 64;

    cudaFuncSetAttribute(k_gru, cudaFuncAttributeMaxDynamicSharedMemorySize, GRU_SMEM);

    cudaLaunchAttribute pdl[1];
    pdl[0].id = cudaLaunchAttributeProgrammaticStreamSerialization;
    pdl[0].val.programmaticStreamSerializationAllowed = 1;

    k_prep_hist<<<(NE4 + 255) / 256, 256>>>(W_conv, W_mix, b_mix, b_conv,
                                            W_ih, W_hh, b_ih, b_hh,
                                            node_idx, hedge_idx, edge_attr);
    k_offsets<<<NBA + NBB, 1024>>>();
    {
        cudaLaunchConfig_t cfg = {};
        cfg.gridDim = dim3((NE4 + 255) / 256);
        cfg.blockDim = dim3(256);
        cfg.attrs = pdl; cfg.numAttrs = 1;
        cudaLaunchKernelEx(&cfg, k_perm, node_idx, hedge_idx, edge_attr);
    }
    {
        cudaLaunchConfig_t cfg = {};
        cfg.gridDim = dim3((NKA * 32 + 255) / 256);
        cfg.blockDim = dim3(256);
        cfg.attrs = pdl; cfg.numAttrs = 1;
        cudaLaunchKernelEx(&cfg, k_gatherA, x);
    }
    {
        cudaLaunchConfig_t cfg = {};
        cfg.gridDim = dim3((NH + 127) / 128, 2);
        cfg.blockDim = dim3(256);
        cfg.attrs = pdl; cfg.numAttrs = 1;
        cudaLaunchKernelEx(&cfg, k_mma_ef);
    }
    {
        cudaLaunchConfig_t cfg = {};
        cfg.gridDim = dim3((NN * 32 + 255) / 256);
        cfg.blockDim = dim3(256);
        cfg.attrs = pdl; cfg.numAttrs = 1;
        cudaLaunchKernelEx(&cfg, k_gatherB);
    }
    {
        cudaLaunchConfig_t cfg = {};
        cfg.gridDim = dim3(GRID_GRU);
        cfg.blockDim = dim3(512);
        cfg.dynamicSmemBytes = GRU_SMEM;
        cfg.attrs = pdl; cfg.numAttrs = 1;
        cudaLaunchKernelEx(&cfg, k_gru, h_prev, W_ro, b_ro, h_next, out3);
    }
}